// round 1
// baseline (speedup 1.0000x reference)
#include <cuda_runtime.h>
#include <cstddef>

#define BATCH 4
#define TSEQ  4096
#define DIM   1024
#define HEADS 16
#define DHEAD 64
#define MROWS (BATCH * TSEQ)          // 16384
#define BHTOT (BATCH * HEADS)         // 64

// ---------------- scratch (static device globals; no allocation) ----------------
__device__ float g_q[(size_t)MROWS * DIM];
__device__ float g_k[(size_t)MROWS * DIM];
__device__ float g_v[(size_t)MROWS * DIM];
__device__ float g_y[(size_t)MROWS * DIM];
__device__ float g_kc[BHTOT * DHEAD];                 // k summed over T, per (b,h,d)
__device__ float g_dinv[(size_t)MROWS * HEADS];       // 1/(q . k_cumsum)
__device__ float g_ctx[BHTOT * DHEAD * DHEAD];        // [bh][d][e]
__device__ float g_ctx_part[8 * BHTOT * DHEAD * DHEAD];

// ---------------- SGEMM: C[M,N] = A[M,K] @ B[K,N] + bias, fp32 ----------------
// 128x128 tile, BK=8, 256 threads, 8x8 per thread (4+4 split), float4 io.
__global__ __launch_bounds__(256, 2)
void sgemm_bias_kernel(const float* __restrict__ A, const float* __restrict__ B,
                       const float* __restrict__ bias, float* __restrict__ C,
                       int M, int N, int K)
{
    const int BK = 8;
    __shared__ float As[BK][132];   // padded: store banks conflict-free
    __shared__ float Bs[BK][128];

    int tid = threadIdx.x;
    int bm = blockIdx.y * 128;
    int bn = blockIdx.x * 128;

    int arow = tid >> 1;            // 0..127
    int acol = (tid & 1) << 2;      // 0 or 4
    int brow = tid >> 5;            // 0..7
    int bcol = (tid & 31) << 2;     // 0..124

    int ta = (tid >> 4) << 2;       // row micro-tile base (0..60)
    int tb = (tid & 15) << 2;       // col micro-tile base (0..60)

    const float* Ap = A + (size_t)(bm + arow) * K + acol;
    const float* Bp = B + (size_t)brow * N + bn + bcol;

    float acc[8][8];
#pragma unroll
    for (int i = 0; i < 8; i++)
#pragma unroll
        for (int j = 0; j < 8; j++) acc[i][j] = 0.f;

    for (int k0 = 0; k0 < K; k0 += BK) {
        float4 av = *(const float4*)(Ap + k0);
        float4 bv = *(const float4*)(Bp + (size_t)k0 * N);
        As[acol + 0][arow] = av.x;
        As[acol + 1][arow] = av.y;
        As[acol + 2][arow] = av.z;
        As[acol + 3][arow] = av.w;
        *(float4*)&Bs[brow][bcol] = bv;
        __syncthreads();
#pragma unroll
        for (int kk = 0; kk < BK; kk++) {
            float4 a0 = *(const float4*)&As[kk][ta];
            float4 a1 = *(const float4*)&As[kk][ta + 64];
            float4 b0 = *(const float4*)&Bs[kk][tb];
            float4 b1 = *(const float4*)&Bs[kk][tb + 64];
            float a[8] = {a0.x, a0.y, a0.z, a0.w, a1.x, a1.y, a1.z, a1.w};
            float bb[8] = {b0.x, b0.y, b0.z, b0.w, b1.x, b1.y, b1.z, b1.w};
#pragma unroll
            for (int i = 0; i < 8; i++)
#pragma unroll
                for (int j = 0; j < 8; j++)
                    acc[i][j] = fmaf(a[i], bb[j], acc[i][j]);
        }
        __syncthreads();
    }

#pragma unroll
    for (int ih = 0; ih < 2; ih++) {
#pragma unroll
        for (int i = 0; i < 4; i++) {
            int row = bm + ta + ih * 64 + i;
#pragma unroll
            for (int jh = 0; jh < 2; jh++) {
                int col = bn + tb + jh * 64;
                float4 o;
                o.x = acc[ih * 4 + i][jh * 4 + 0] + bias[col + 0];
                o.y = acc[ih * 4 + i][jh * 4 + 1] + bias[col + 1];
                o.z = acc[ih * 4 + i][jh * 4 + 2] + bias[col + 2];
                o.w = acc[ih * 4 + i][jh * 4 + 3] + bias[col + 3];
                *(float4*)&C[(size_t)row * N + col] = o;
            }
        }
    }
}

// ---------------- softmax over head dim (64) in place ----------------
// one warp per (row, head); lane covers d and d+32
__global__ void softmax64_kernel(float* __restrict__ data)
{
    int gt = blockIdx.x * blockDim.x + threadIdx.x;
    int w = gt >> 5;
    int lane = threadIdx.x & 31;
    int row = w >> 4;
    int h = w & 15;
    float* p = data + (size_t)row * DIM + h * DHEAD;
    float v0 = p[lane], v1 = p[lane + 32];
    float m = fmaxf(v0, v1);
#pragma unroll
    for (int off = 16; off > 0; off >>= 1)
        m = fmaxf(m, __shfl_xor_sync(0xffffffffu, m, off));
    float e0 = __expf(v0 - m), e1 = __expf(v1 - m);
    float s = e0 + e1;
#pragma unroll
    for (int off = 16; off > 0; off >>= 1)
        s += __shfl_xor_sync(0xffffffffu, s, off);
    float inv = 1.f / s;
    p[lane] = e0 * inv;
    p[lane + 32] = e1 * inv;
}

// ---------------- k_cumsum over T ----------------
// one block per (b,h); 256 threads: d = tid&63, t-chunk = tid>>6
__global__ void kcumsum_kernel(const float* __restrict__ k, float* __restrict__ kc)
{
    int bh = blockIdx.x;
    int b = bh >> 4, h = bh & 15;
    int d = threadIdx.x & 63;
    int chunk = threadIdx.x >> 6;
    const float* base = k + (size_t)(b * TSEQ + chunk * 1024) * DIM + h * DHEAD + d;
    float s = 0.f;
#pragma unroll 8
    for (int t = 0; t < 1024; t++) s += base[(size_t)t * DIM];
    __shared__ float sm[256];
    sm[threadIdx.x] = s;
    __syncthreads();
    if (threadIdx.x < 64)
        kc[bh * DHEAD + d] = sm[d] + sm[64 + d] + sm[128 + d] + sm[192 + d];
}

// ---------------- D_inv = 1 / (q . k_cumsum) ----------------
__global__ void dinv_kernel(const float* __restrict__ q, const float* __restrict__ kc,
                            float* __restrict__ dinv)
{
    int gt = blockIdx.x * blockDim.x + threadIdx.x;
    int w = gt >> 5;
    int lane = threadIdx.x & 31;
    int row = w >> 4;
    int h = w & 15;
    int b = row >> 12;  // row / 4096
    const float* qp = q + (size_t)row * DIM + h * DHEAD;
    const float* kp = kc + (b * HEADS + h) * DHEAD;
    float s = qp[lane] * kp[lane] + qp[lane + 32] * kp[lane + 32];
#pragma unroll
    for (int off = 16; off > 0; off >>= 1)
        s += __shfl_xor_sync(0xffffffffu, s, off);
    if (lane == 0) dinv[(size_t)row * HEADS + h] = 1.f / s;
}

// ---------------- context partial: ctx_p[d][e] += k[t][d]*v[t][e] over 512 t ----------------
// grid (8 chunks, 64 bh), 256 threads, each thread 4x4 outputs
__global__ void ctx_partial_kernel(const float* __restrict__ k, const float* __restrict__ v,
                                   float* __restrict__ part)
{
    int chunk = blockIdx.x;
    int bh = blockIdx.y;
    int b = bh >> 4, h = bh & 15;
    int t0 = chunk * 512;
    __shared__ float ks[32][64];
    __shared__ float vs[32][64];
    int tid = threadIdx.x;
    int d0 = (tid >> 4) << 2;
    int e0 = (tid & 15) << 2;
    float acc[4][4];
#pragma unroll
    for (int i = 0; i < 4; i++)
#pragma unroll
        for (int j = 0; j < 4; j++) acc[i][j] = 0.f;

    for (int tt = 0; tt < 512; tt += 32) {
#pragma unroll
        for (int l = 0; l < 2; l++) {
            int idx = tid + l * 256;
            int r = idx >> 4;
            int c = (idx & 15) << 2;
            size_t g = (size_t)(b * TSEQ + t0 + tt + r) * DIM + h * DHEAD + c;
            *(float4*)&ks[r][c] = *(const float4*)(k + g);
            *(float4*)&vs[r][c] = *(const float4*)(v + g);
        }
        __syncthreads();
#pragma unroll 8
        for (int t = 0; t < 32; t++) {
            float4 ka = *(const float4*)&ks[t][d0];
            float4 vb = *(const float4*)&vs[t][e0];
            float a[4] = {ka.x, ka.y, ka.z, ka.w};
            float bb[4] = {vb.x, vb.y, vb.z, vb.w};
#pragma unroll
            for (int i = 0; i < 4; i++)
#pragma unroll
                for (int j = 0; j < 4; j++)
                    acc[i][j] = fmaf(a[i], bb[j], acc[i][j]);
        }
        __syncthreads();
    }
    float* outp = part + ((size_t)chunk * BHTOT + bh) * DHEAD * DHEAD;
#pragma unroll
    for (int i = 0; i < 4; i++)
        *(float4*)&outp[(d0 + i) * DHEAD + e0] =
            make_float4(acc[i][0], acc[i][1], acc[i][2], acc[i][3]);
}

__global__ void ctx_reduce_kernel(const float* __restrict__ part, float* __restrict__ ctx)
{
    int i = blockIdx.x * blockDim.x + threadIdx.x;  // 0..262143
    const size_t stride = (size_t)BHTOT * DHEAD * DHEAD;
    float s = 0.f;
#pragma unroll
    for (int c = 0; c < 8; c++) s += part[c * stride + i];
    ctx[i] = s;
}

// ---------------- y = (q @ ctx) * dinv + q, written in merged-head layout ----------------
// grid (64 t-tiles, 64 bh), 256 threads
__global__ void apply_kernel(const float* __restrict__ q, const float* __restrict__ ctx,
                             const float* __restrict__ dinv, float* __restrict__ y)
{
    int bh = blockIdx.y;
    int b = bh >> 4, h = bh & 15;
    int t0 = blockIdx.x * 64;
    __shared__ float cs[64][64];
    __shared__ float qs[64][64];
    int tid = threadIdx.x;

    const float4* cp = (const float4*)(ctx + (size_t)bh * DHEAD * DHEAD);
#pragma unroll
    for (int l = 0; l < 4; l++)
        ((float4*)cs)[tid + l * 256] = cp[tid + l * 256];
#pragma unroll
    for (int l = 0; l < 4; l++) {
        int idx = tid + l * 256;
        int r = idx >> 4;
        int c = (idx & 15) << 2;
        *(float4*)&qs[r][c] =
            *(const float4*)(q + (size_t)(b * TSEQ + t0 + r) * DIM + h * DHEAD + c);
    }
    __syncthreads();

    int wid = tid >> 5, lane = tid & 31;
#pragma unroll
    for (int rr = 0; rr < 8; rr++) {
        int r = wid * 8 + rr;
        float a0 = 0.f, a1 = 0.f;
#pragma unroll
        for (int d = 0; d < 64; d++) {
            float qv = qs[r][d];
            a0 = fmaf(qv, cs[d][lane], a0);
            a1 = fmaf(qv, cs[d][lane + 32], a1);
        }
        int grow = b * TSEQ + t0 + r;
        float di = dinv[(size_t)grow * HEADS + h];
        float* yp = y + (size_t)grow * DIM + h * DHEAD;
        yp[lane] = a0 * di + qs[r][lane];
        yp[lane + 32] = a1 * di + qs[r][lane + 32];
    }
}

// ---------------- launch ----------------
extern "C" void kernel_launch(void* const* d_in, const int* in_sizes, int n_in,
                              void* d_out, int out_size)
{
    const float* x  = (const float*)d_in[0];
    const float* Wq = (const float*)d_in[1];
    const float* bq = (const float*)d_in[2];
    const float* Wk = (const float*)d_in[3];
    const float* bk = (const float*)d_in[4];
    const float* Wv = (const float*)d_in[5];
    const float* bv = (const float*)d_in[6];
    const float* Wp = (const float*)d_in[7];
    const float* bp = (const float*)d_in[8];
    float* out = (float*)d_out;

    float *pq, *pk, *pv, *py, *pkc, *pdinv, *pctx, *ppart;
    cudaGetSymbolAddress((void**)&pq, g_q);
    cudaGetSymbolAddress((void**)&pk, g_k);
    cudaGetSymbolAddress((void**)&pv, g_v);
    cudaGetSymbolAddress((void**)&py, g_y);
    cudaGetSymbolAddress((void**)&pkc, g_kc);
    cudaGetSymbolAddress((void**)&pdinv, g_dinv);
    cudaGetSymbolAddress((void**)&pctx, g_ctx);
    cudaGetSymbolAddress((void**)&ppart, g_ctx_part);

    dim3 gemm_grid(DIM / 128, MROWS / 128);   // (8, 128)
    sgemm_bias_kernel<<<gemm_grid, 256>>>(x, Wq, bq, pq, MROWS, DIM, DIM);
    sgemm_bias_kernel<<<gemm_grid, 256>>>(x, Wk, bk, pk, MROWS, DIM, DIM);
    sgemm_bias_kernel<<<gemm_grid, 256>>>(x, Wv, bv, pv, MROWS, DIM, DIM);

    int sm_blocks = (MROWS * HEADS * 32) / 256;  // 32768
    softmax64_kernel<<<sm_blocks, 256>>>(pq);
    softmax64_kernel<<<sm_blocks, 256>>>(pk);

    kcumsum_kernel<<<BHTOT, 256>>>(pk, pkc);
    dinv_kernel<<<sm_blocks, 256>>>(pq, pkc, pdinv);

    ctx_partial_kernel<<<dim3(8, BHTOT), 256>>>(pk, pv, ppart);
    ctx_reduce_kernel<<<(BHTOT * DHEAD * DHEAD) / 256, 256>>>(ppart, pctx);

    apply_kernel<<<dim3(TSEQ / 64, BHTOT), 256>>>(pq, pctx, pdinv, py);

    sgemm_bias_kernel<<<gemm_grid, 256>>>(py, Wp, bp, out, MROWS, DIM, DIM);
}

// round 13
// speedup vs baseline: 1.9037x; 1.9037x over previous
#include <cuda_runtime.h>
#include <cuda_bf16.h>
#include <cstdint>
#include <cstddef>

#define BATCH 4
#define TSEQ  4096
#define DIM   1024
#define HEADS 16
#define DHEAD 64
#define MROWS (BATCH * TSEQ)          // 16384
#define BHTOT (BATCH * HEADS)         // 64
#define KTOT  2048                    // hi|lo concatenated
#define NCHUNK 48                     // 3 terms * 16 k-chunks of 64
#define GEMM_SMEM 65536               // A[2][16KB] + B[2][16KB]
#define SA(s) ((s) * 16384)
#define SB(s) (32768 + (s) * 16384)

// ---------------- scratch (static device globals; no allocation) ----------------
__device__ float g_q[(size_t)MROWS * DIM];
__device__ float g_k[(size_t)MROWS * DIM];
__device__ float g_v[(size_t)MROWS * DIM];
__device__ float g_y[(size_t)MROWS * DIM];
__device__ float g_kc[BHTOT * DHEAD];
__device__ float g_dinv[(size_t)MROWS * HEADS];
__device__ float g_ctx[BHTOT * DHEAD * DHEAD];
__device__ float g_ctx_part[8 * BHTOT * DHEAD * DHEAD];
__device__ __nv_bfloat16 g_split[(size_t)MROWS * KTOT];
__device__ __nv_bfloat16 g_wt[4][(size_t)DIM * KTOT];

// ================= PTX helpers (all plain sm_80-era features) =================
__device__ __forceinline__ uint32_t smem_u32(const void* p) {
    uint32_t a;
    asm("{ .reg .u64 t; cvta.to.shared.u64 t, %1; cvt.u32.u64 %0, t; }" : "=r"(a) : "l"(p));
    return a;
}
__device__ __forceinline__ void cp16(uint32_t sa, const void* ga) {
    asm volatile("cp.async.cg.shared.global [%0], [%1], 16;" :: "r"(sa), "l"(ga) : "memory");
}
__device__ __forceinline__ void ldm4(uint32_t* r, uint32_t addr) {
    asm volatile("ldmatrix.sync.aligned.m8n8.x4.shared.b16 {%0,%1,%2,%3}, [%4];"
                 : "=r"(r[0]), "=r"(r[1]), "=r"(r[2]), "=r"(r[3]) : "r"(addr));
}
__device__ __forceinline__ void mma16816(float* c, const uint32_t* a, const uint32_t* b) {
    asm volatile("mma.sync.aligned.m16n8k16.row.col.f32.bf16.bf16.f32 "
                 "{%0,%1,%2,%3}, {%4,%5,%6,%7}, {%8,%9}, {%0,%1,%2,%3};"
                 : "+f"(c[0]), "+f"(c[1]), "+f"(c[2]), "+f"(c[3])
                 : "r"(a[0]), "r"(a[1]), "r"(a[2]), "r"(a[3]), "r"(b[0]), "r"(b[1]));
}

// loader: A tile 128x64 bf16 + B tile 128x64 bf16 into stage s, SW128 swizzled
__device__ __forceinline__ void produce_chunk(const __nv_bfloat16* __restrict__ agbase,
                                              const __nv_bfloat16* __restrict__ bgbase,
                                              uint32_t sb, const uint32_t* loff, int chunk)
{
    int t = chunk >> 4, kc = chunk & 15;
    int aoff = (t == 1 ? 1024 : 0) + kc * 64;
    int boff = (t == 2 ? 1024 : 0) + kc * 64;
    int s = chunk & 1;
    uint32_t abase = sb + SA(s), bbase = sb + SB(s);
#pragma unroll
    for (int g = 0; g < 4; g++) {
        cp16(abase + loff[g], agbase + aoff + g * 8);
        cp16(bbase + loff[g], bgbase + boff + g * 8);
    }
    asm volatile("cp.async.commit_group;" ::: "memory");
}

// ================= bf16 split-GEMM via mma.sync =================
// C[M,1024] = A'[M,hi|lo] x Wt'[N,hi|lo]^T + bias (3-term hi/lo schedule)
__global__ __launch_bounds__(256)
void gemm_bf16_kernel(const __nv_bfloat16* __restrict__ A, const __nv_bfloat16* __restrict__ B,
                      const float* __restrict__ bias, float* __restrict__ C)
{
    extern __shared__ __align__(1024) char smem[];
    uint32_t sb = smem_u32(smem);
    int tid = threadIdx.x;
    int bm = blockIdx.y * 128;
    int bn = blockIdx.x * 128;

    // ---- loader indices: row = tid>>1 (0..127), half = tid&1 (64B each)
    int lrow = tid >> 1, lhalf = tid & 1;
    const __nv_bfloat16* agbase = A + (size_t)(bm + lrow) * KTOT + lhalf * 32;
    const __nv_bfloat16* bgbase = B + (size_t)(bn + lrow) * KTOT + lhalf * 32;
    uint32_t loff[4];
#pragma unroll
    for (int g = 0; g < 4; g++)
        loff[g] = (uint32_t)(lrow * 128 + lhalf * 64 + g * 16) ^ ((uint32_t)(lrow & 7) << 4);

    // ---- compute indices
    int lane = tid & 31, warp = tid >> 5;
    int wm = (warp & 3) * 32;       // warp m-base (2 m16 tiles)
    int wn = (warp >> 2) * 64;      // warp n-base (8 n8 tiles)
    int sel = lane >> 3, lr = lane & 7;
    uint32_t xorv = (uint32_t)lr << 4;
    // A: matrix order (m0,k0),(m8,k0),(m0,k8),(m8,k8)
    int arow = wm + (sel & 1) * 8 + lr;
    uint32_t arowterm0 = (uint32_t)arow * 128;
    uint32_t arowterm1 = (uint32_t)(arow + 16) * 128;
    uint32_t ak2 = (uint32_t)((sel >> 1) * 8) * 2;
    // B: matrix order (n0,k0),(n0,k8),(n8,k0),(n8,k8)
    int brow = wn + (sel >> 1) * 8 + lr;
    uint32_t bk2 = (uint32_t)((sel & 1) * 8) * 2;
    uint32_t browterm[4];
#pragma unroll
    for (int bt = 0; bt < 4; bt++) browterm[bt] = (uint32_t)(brow + bt * 16) * 128;

    float acc[2][8][4];
#pragma unroll
    for (int i = 0; i < 2; i++)
#pragma unroll
        for (int j = 0; j < 8; j++)
#pragma unroll
            for (int q = 0; q < 4; q++) acc[i][j][q] = 0.f;

    produce_chunk(agbase, bgbase, sb, loff, 0);

    for (int j = 0; j < NCHUNK; j++) {
        asm volatile("cp.async.wait_group 0;" ::: "memory");
        __syncthreads();
        if (j + 1 < NCHUNK) produce_chunk(agbase, bgbase, sb, loff, j + 1);

        uint32_t as = sb + SA(j & 1);
        uint32_t bs = sb + SB(j & 1);
#pragma unroll
        for (uint32_t kb2 = 0; kb2 < 128; kb2 += 32) {   // 4 k16 steps (bytes)
            uint32_t af0[4], af1[4], bf[4][4];
            ldm4(af0, as + ((arowterm0 + ak2 + kb2) ^ xorv));
            ldm4(af1, as + ((arowterm1 + ak2 + kb2) ^ xorv));
#pragma unroll
            for (int bt = 0; bt < 4; bt++)
                ldm4(bf[bt], bs + ((browterm[bt] + bk2 + kb2) ^ xorv));
#pragma unroll
            for (int nt = 0; nt < 8; nt++) {
                const uint32_t* bfr = &bf[nt >> 1][(nt & 1) * 2];
                mma16816(acc[0][nt], af0, bfr);
                mma16816(acc[1][nt], af1, bfr);
            }
        }
    }

    // ---- epilogue: c0,c1 at (g, 2t), c2,c3 at (g+8, 2t), + bias
    int g = lane >> 2, t4 = lane & 3;
#pragma unroll
    for (int mt = 0; mt < 2; mt++) {
        int row = bm + wm + mt * 16 + g;
#pragma unroll
        for (int nt = 0; nt < 8; nt++) {
            int col = bn + wn + nt * 8 + t4 * 2;
            float b0 = bias[col], b1 = bias[col + 1];
            float2 o0 = make_float2(acc[mt][nt][0] + b0, acc[mt][nt][1] + b1);
            float2 o1 = make_float2(acc[mt][nt][2] + b0, acc[mt][nt][3] + b1);
            *(float2*)(C + (size_t)row * DIM + col) = o0;
            *(float2*)(C + (size_t)(row + 8) * DIM + col) = o1;
        }
    }
}

// ================= prep kernels =================
__global__ void split_kernel(const float* __restrict__ in, __nv_bfloat16* __restrict__ o)
{
    size_t i = (size_t)blockIdx.x * 256 + threadIdx.x;
    size_t row = i >> 8;
    int c4 = (int)(i & 255) * 4;
    float4 v = *(const float4*)(in + row * DIM + c4);
    __nv_bfloat16 h0 = __float2bfloat16(v.x), h1 = __float2bfloat16(v.y);
    __nv_bfloat16 h2 = __float2bfloat16(v.z), h3 = __float2bfloat16(v.w);
    __nv_bfloat16 l0 = __float2bfloat16(v.x - __bfloat162float(h0));
    __nv_bfloat16 l1 = __float2bfloat16(v.y - __bfloat162float(h1));
    __nv_bfloat16 l2 = __float2bfloat16(v.z - __bfloat162float(h2));
    __nv_bfloat16 l3 = __float2bfloat16(v.w - __bfloat162float(h3));
    __nv_bfloat162* ph = (__nv_bfloat162*)(o + row * KTOT + c4);
    ph[0] = __halves2bfloat162(h0, h1);
    ph[1] = __halves2bfloat162(h2, h3);
    __nv_bfloat162* pl = (__nv_bfloat162*)(o + row * KTOT + 1024 + c4);
    pl[0] = __halves2bfloat162(l0, l1);
    pl[1] = __halves2bfloat162(l2, l3);
}

__global__ void wsplit_kernel(const float* __restrict__ W, __nv_bfloat16* __restrict__ Wt)
{
    __shared__ float sm[32][33];
    int n0 = blockIdx.x * 32, k0 = blockIdx.y * 32;
    int tid = threadIdx.x;
#pragma unroll
    for (int l = 0; l < 4; l++) {
        int idx = tid + l * 256;
        int r = idx >> 5, c = idx & 31;
        sm[r][c] = W[(size_t)(k0 + r) * DIM + n0 + c];
    }
    __syncthreads();
#pragma unroll
    for (int l = 0; l < 4; l++) {
        int idx = tid + l * 256;
        int r = idx >> 5, c = idx & 31;
        float v = sm[c][r];
        __nv_bfloat16 h = __float2bfloat16(v);
        __nv_bfloat16 lo = __float2bfloat16(v - __bfloat162float(h));
        Wt[(size_t)(n0 + r) * KTOT + k0 + c] = h;
        Wt[(size_t)(n0 + r) * KTOT + 1024 + k0 + c] = lo;
    }
}

// ================= attention mid-section (fp32) =================
__global__ void softmax64_kernel(float* __restrict__ data)
{
    int gt = blockIdx.x * blockDim.x + threadIdx.x;
    int w = gt >> 5;
    int lane = threadIdx.x & 31;
    int row = w >> 4;
    int h = w & 15;
    float* p = data + (size_t)row * DIM + h * DHEAD;
    float v0 = p[lane], v1 = p[lane + 32];
    float m = fmaxf(v0, v1);
#pragma unroll
    for (int off = 16; off > 0; off >>= 1)
        m = fmaxf(m, __shfl_xor_sync(0xffffffffu, m, off));
    float e0 = __expf(v0 - m), e1 = __expf(v1 - m);
    float s = e0 + e1;
#pragma unroll
    for (int off = 16; off > 0; off >>= 1)
        s += __shfl_xor_sync(0xffffffffu, s, off);
    float inv = 1.f / s;
    p[lane] = e0 * inv;
    p[lane + 32] = e1 * inv;
}

__global__ void kcumsum_kernel(const float* __restrict__ k, float* __restrict__ kc)
{
    int bh = blockIdx.x;
    int b = bh >> 4, h = bh & 15;
    int d = threadIdx.x & 63;
    int chunk = threadIdx.x >> 6;
    const float* base = k + (size_t)(b * TSEQ + chunk * 1024) * DIM + h * DHEAD + d;
    float s = 0.f;
#pragma unroll 8
    for (int t = 0; t < 1024; t++) s += base[(size_t)t * DIM];
    __shared__ float sm[256];
    sm[threadIdx.x] = s;
    __syncthreads();
    if (threadIdx.x < 64)
        kc[bh * DHEAD + d] = sm[d] + sm[64 + d] + sm[128 + d] + sm[192 + d];
}

__global__ void dinv_kernel(const float* __restrict__ q, const float* __restrict__ kc,
                            float* __restrict__ dinv)
{
    int gt = blockIdx.x * blockDim.x + threadIdx.x;
    int w = gt >> 5;
    int lane = threadIdx.x & 31;
    int row = w >> 4;
    int h = w & 15;
    int b = row >> 12;
    const float* qp = q + (size_t)row * DIM + h * DHEAD;
    const float* kp = kc + (b * HEADS + h) * DHEAD;
    float s = qp[lane] * kp[lane] + qp[lane + 32] * kp[lane + 32];
#pragma unroll
    for (int off = 16; off > 0; off >>= 1)
        s += __shfl_xor_sync(0xffffffffu, s, off);
    if (lane == 0) dinv[(size_t)row * HEADS + h] = 1.f / s;
}

__global__ void ctx_partial_kernel(const float* __restrict__ k, const float* __restrict__ v,
                                   float* __restrict__ part)
{
    int chunk = blockIdx.x;
    int bh = blockIdx.y;
    int b = bh >> 4, h = bh & 15;
    int t0 = chunk * 512;
    __shared__ float ks[32][64];
    __shared__ float vs[32][64];
    int tid = threadIdx.x;
    int d0 = (tid >> 4) << 2;
    int e0 = (tid & 15) << 2;
    float acc[4][4];
#pragma unroll
    for (int i = 0; i < 4; i++)
#pragma unroll
        for (int j = 0; j < 4; j++) acc[i][j] = 0.f;

    for (int tt = 0; tt < 512; tt += 32) {
#pragma unroll
        for (int l = 0; l < 2; l++) {
            int idx = tid + l * 256;
            int r = idx >> 4;
            int c = (idx & 15) << 2;
            size_t g = (size_t)(b * TSEQ + t0 + tt + r) * DIM + h * DHEAD + c;
            *(float4*)&ks[r][c] = *(const float4*)(k + g);
            *(float4*)&vs[r][c] = *(const float4*)(v + g);
        }
        __syncthreads();
#pragma unroll 8
        for (int t = 0; t < 32; t++) {
            float4 ka = *(const float4*)&ks[t][d0];
            float4 vb = *(const float4*)&vs[t][e0];
            float a[4] = {ka.x, ka.y, ka.z, ka.w};
            float bb[4] = {vb.x, vb.y, vb.z, vb.w};
#pragma unroll
            for (int i = 0; i < 4; i++)
#pragma unroll
                for (int j = 0; j < 4; j++)
                    acc[i][j] = fmaf(a[i], bb[j], acc[i][j]);
        }
        __syncthreads();
    }
    float* outp = part + ((size_t)chunk * BHTOT + bh) * DHEAD * DHEAD;
#pragma unroll
    for (int i = 0; i < 4; i++)
        *(float4*)&outp[(d0 + i) * DHEAD + e0] =
            make_float4(acc[i][0], acc[i][1], acc[i][2], acc[i][3]);
}

__global__ void ctx_reduce_kernel(const float* __restrict__ part, float* __restrict__ ctx)
{
    int i = blockIdx.x * blockDim.x + threadIdx.x;
    const size_t stride = (size_t)BHTOT * DHEAD * DHEAD;
    float s = 0.f;
#pragma unroll
    for (int c = 0; c < 8; c++) s += part[c * stride + i];
    ctx[i] = s;
}

__global__ void apply_kernel(const float* __restrict__ q, const float* __restrict__ ctx,
                             const float* __restrict__ dinv, float* __restrict__ y)
{
    int bh = blockIdx.y;
    int b = bh >> 4, h = bh & 15;
    int t0 = blockIdx.x * 64;
    __shared__ float cs[64][64];
    __shared__ float qs[64][64];
    int tid = threadIdx.x;

    const float4* cp = (const float4*)(ctx + (size_t)bh * DHEAD * DHEAD);
#pragma unroll
    for (int l = 0; l < 4; l++)
        ((float4*)cs)[tid + l * 256] = cp[tid + l * 256];
#pragma unroll
    for (int l = 0; l < 4; l++) {
        int idx = tid + l * 256;
        int r = idx >> 4;
        int c = (idx & 15) << 2;
        *(float4*)&qs[r][c] =
            *(const float4*)(q + (size_t)(b * TSEQ + t0 + r) * DIM + h * DHEAD + c);
    }
    __syncthreads();

    int wid = tid >> 5, lane = tid & 31;
#pragma unroll
    for (int rr = 0; rr < 8; rr++) {
        int r = wid * 8 + rr;
        float a0 = 0.f, a1 = 0.f;
#pragma unroll
        for (int d = 0; d < 64; d++) {
            float qv = qs[r][d];
            a0 = fmaf(qv, cs[d][lane], a0);
            a1 = fmaf(qv, cs[d][lane + 32], a1);
        }
        int grow = b * TSEQ + t0 + r;
        float di = dinv[(size_t)grow * HEADS + h];
        float* yp = y + (size_t)grow * DIM + h * DHEAD;
        yp[lane] = a0 * di + qs[r][lane];
        yp[lane + 32] = a1 * di + qs[r][lane + 32];
    }
}

// ================= launch =================
extern "C" void kernel_launch(void* const* d_in, const int* in_sizes, int n_in,
                              void* d_out, int out_size)
{
    const float* x  = (const float*)d_in[0];
    const float* Wq = (const float*)d_in[1];
    const float* bq = (const float*)d_in[2];
    const float* Wk = (const float*)d_in[3];
    const float* bk = (const float*)d_in[4];
    const float* Wv = (const float*)d_in[5];
    const float* bv = (const float*)d_in[6];
    const float* Wp = (const float*)d_in[7];
    const float* bp = (const float*)d_in[8];
    float* out = (float*)d_out;

    float *pq, *pk, *pv, *py, *pkc, *pdinv, *pctx, *ppart;
    __nv_bfloat16 *psplit, *pwt;
    cudaGetSymbolAddress((void**)&pq, g_q);
    cudaGetSymbolAddress((void**)&pk, g_k);
    cudaGetSymbolAddress((void**)&pv, g_v);
    cudaGetSymbolAddress((void**)&py, g_y);
    cudaGetSymbolAddress((void**)&pkc, g_kc);
    cudaGetSymbolAddress((void**)&pdinv, g_dinv);
    cudaGetSymbolAddress((void**)&pctx, g_ctx);
    cudaGetSymbolAddress((void**)&ppart, g_ctx_part);
    cudaGetSymbolAddress((void**)&psplit, g_split);
    cudaGetSymbolAddress((void**)&pwt, g_wt);
    __nv_bfloat16* wt0 = pwt;
    __nv_bfloat16* wt1 = pwt + (size_t)DIM * KTOT;
    __nv_bfloat16* wt2 = pwt + 2 * (size_t)DIM * KTOT;
    __nv_bfloat16* wt3 = pwt + 3 * (size_t)DIM * KTOT;

    cudaFuncSetAttribute(gemm_bf16_kernel,
                         cudaFuncAttributeMaxDynamicSharedMemorySize, GEMM_SMEM);

    split_kernel<<<MROWS * DIM / 1024, 256>>>(x, psplit);
    wsplit_kernel<<<dim3(32, 32), 256>>>(Wq, wt0);
    wsplit_kernel<<<dim3(32, 32), 256>>>(Wk, wt1);
    wsplit_kernel<<<dim3(32, 32), 256>>>(Wv, wt2);
    wsplit_kernel<<<dim3(32, 32), 256>>>(Wp, wt3);

    dim3 ggrid(DIM / 128, MROWS / 128);   // (8, 128)
    gemm_bf16_kernel<<<ggrid, 256, GEMM_SMEM>>>(psplit, wt0, bq, pq);
    gemm_bf16_kernel<<<ggrid, 256, GEMM_SMEM>>>(psplit, wt1, bk, pk);
    gemm_bf16_kernel<<<ggrid, 256, GEMM_SMEM>>>(psplit, wt2, bv, pv);

    int sm_blocks = (MROWS * HEADS * 32) / 256;
    softmax64_kernel<<<sm_blocks, 256>>>(pq);
    softmax64_kernel<<<sm_blocks, 256>>>(pk);
    kcumsum_kernel<<<BHTOT, 256>>>(pk, pkc);
    dinv_kernel<<<sm_blocks, 256>>>(pq, pkc, pdinv);
    ctx_partial_kernel<<<dim3(8, BHTOT), 256>>>(pk, pv, ppart);
    ctx_reduce_kernel<<<(BHTOT * DHEAD * DHEAD) / 256, 256>>>(ppart, pctx);
    apply_kernel<<<dim3(TSEQ / 64, BHTOT), 256>>>(pq, pctx, pdinv, py);

    split_kernel<<<MROWS * DIM / 1024, 256>>>(py, psplit);
    gemm_bf16_kernel<<<ggrid, 256, GEMM_SMEM>>>(psplit, wt3, bp, out);
}

// round 15
// speedup vs baseline: 1.9581x; 1.0286x over previous
#include <cuda_runtime.h>
#include <cuda_bf16.h>
#include <cstdint>
#include <cstddef>

#define BATCH 4
#define TSEQ  4096
#define DIM   1024
#define HEADS 16
#define DHEAD 64
#define MROWS (BATCH * TSEQ)          // 16384
#define BHTOT (BATCH * HEADS)         // 64
#define KTOT  2048                    // hi|lo concatenated
#define NCHUNK 48                     // 3 terms * 16 k-chunks of 64
#define NSTAGE 3
#define GEMM_SMEM 98304               // A[3][16KB] + B[3][16KB]
#define SA(s) ((s) * 16384)
#define SB(s) (49152 + (s) * 16384)

// ---------------- scratch (static device globals; no allocation) ----------------
__device__ float g_q[(size_t)MROWS * DIM];
__device__ float g_k[(size_t)MROWS * DIM];
__device__ float g_v[(size_t)MROWS * DIM];
__device__ float g_kc[BHTOT * DHEAD];
__device__ float g_ctx[BHTOT * DHEAD * DHEAD];
__device__ float g_ctx_part[8 * BHTOT * DHEAD * DHEAD];
__device__ __nv_bfloat16 g_split[(size_t)MROWS * KTOT];
__device__ __nv_bfloat16 g_wt[4][(size_t)DIM * KTOT];

// ================= PTX helpers (all plain sm_80-era features) =================
__device__ __forceinline__ uint32_t smem_u32(const void* p) {
    uint32_t a;
    asm("{ .reg .u64 t; cvta.to.shared.u64 t, %1; cvt.u32.u64 %0, t; }" : "=r"(a) : "l"(p));
    return a;
}
__device__ __forceinline__ void cp16(uint32_t sa, const void* ga) {
    asm volatile("cp.async.cg.shared.global [%0], [%1], 16;" :: "r"(sa), "l"(ga) : "memory");
}
__device__ __forceinline__ void ldm4(uint32_t* r, uint32_t addr) {
    asm volatile("ldmatrix.sync.aligned.m8n8.x4.shared.b16 {%0,%1,%2,%3}, [%4];"
                 : "=r"(r[0]), "=r"(r[1]), "=r"(r[2]), "=r"(r[3]) : "r"(addr));
}
__device__ __forceinline__ void mma16816(float* c, const uint32_t* a, const uint32_t* b) {
    asm volatile("mma.sync.aligned.m16n8k16.row.col.f32.bf16.bf16.f32 "
                 "{%0,%1,%2,%3}, {%4,%5,%6,%7}, {%8,%9}, {%0,%1,%2,%3};"
                 : "+f"(c[0]), "+f"(c[1]), "+f"(c[2]), "+f"(c[3])
                 : "r"(a[0]), "r"(a[1]), "r"(a[2]), "r"(a[3]), "r"(b[0]), "r"(b[1]));
}

// loader: A tile 128x64 bf16 + B tile 128x64 bf16 into stage chunk%3, SW128 swizzled
__device__ __forceinline__ void produce_chunk(const __nv_bfloat16* __restrict__ agbase,
                                              const __nv_bfloat16* __restrict__ bgbase,
                                              uint32_t sb, const uint32_t* loff, int chunk)
{
    int t = chunk >> 4, kc = chunk & 15;
    int aoff = (t == 1 ? 1024 : 0) + kc * 64;
    int boff = (t == 2 ? 1024 : 0) + kc * 64;
    int s = chunk % NSTAGE;
    uint32_t abase = sb + SA(s), bbase = sb + SB(s);
#pragma unroll
    for (int g = 0; g < 4; g++) {
        cp16(abase + loff[g], agbase + aoff + g * 8);
        cp16(bbase + loff[g], bgbase + boff + g * 8);
    }
    asm volatile("cp.async.commit_group;" ::: "memory");
}

// ================= bf16 split-GEMM via mma.sync (3-stage pipeline) =================
__global__ __launch_bounds__(256)
void gemm_bf16_kernel(const __nv_bfloat16* __restrict__ A, const __nv_bfloat16* __restrict__ B,
                      const float* __restrict__ bias, float* __restrict__ C)
{
    extern __shared__ __align__(1024) char smem[];
    uint32_t sb = smem_u32(smem);
    int tid = threadIdx.x;
    int bm = blockIdx.y * 128;
    int bn = blockIdx.x * 128;

    int lrow = tid >> 1, lhalf = tid & 1;
    const __nv_bfloat16* agbase = A + (size_t)(bm + lrow) * KTOT + lhalf * 32;
    const __nv_bfloat16* bgbase = B + (size_t)(bn + lrow) * KTOT + lhalf * 32;
    uint32_t loff[4];
#pragma unroll
    for (int g = 0; g < 4; g++)
        loff[g] = (uint32_t)(lrow * 128 + lhalf * 64 + g * 16) ^ ((uint32_t)(lrow & 7) << 4);

    int lane = tid & 31, warp = tid >> 5;
    int wm = (warp & 3) * 32;
    int wn = (warp >> 2) * 64;
    int sel = lane >> 3, lr = lane & 7;
    uint32_t xorv = (uint32_t)lr << 4;
    int arow = wm + (sel & 1) * 8 + lr;
    uint32_t arowterm0 = (uint32_t)arow * 128;
    uint32_t arowterm1 = (uint32_t)(arow + 16) * 128;
    uint32_t ak2 = (uint32_t)((sel >> 1) * 8) * 2;
    int brow = wn + (sel >> 1) * 8 + lr;
    uint32_t bk2 = (uint32_t)((sel & 1) * 8) * 2;
    uint32_t browterm[4];
#pragma unroll
    for (int bt = 0; bt < 4; bt++) browterm[bt] = (uint32_t)(brow + bt * 16) * 128;

    float acc[2][8][4];
#pragma unroll
    for (int i = 0; i < 2; i++)
#pragma unroll
        for (int j = 0; j < 8; j++)
#pragma unroll
            for (int q = 0; q < 4; q++) acc[i][j][q] = 0.f;

    produce_chunk(agbase, bgbase, sb, loff, 0);
    produce_chunk(agbase, bgbase, sb, loff, 1);

    for (int j = 0; j < NCHUNK; j++) {
        if (j < NCHUNK - 1) asm volatile("cp.async.wait_group 1;" ::: "memory");
        else                asm volatile("cp.async.wait_group 0;" ::: "memory");
        __syncthreads();
        if (j + 2 < NCHUNK) produce_chunk(agbase, bgbase, sb, loff, j + 2);

        int s = j % NSTAGE;
        uint32_t as = sb + SA(s);
        uint32_t bs = sb + SB(s);
#pragma unroll
        for (uint32_t kb2 = 0; kb2 < 128; kb2 += 32) {
            uint32_t af0[4], af1[4], bf[4][4];
            ldm4(af0, as + ((arowterm0 + ak2 + kb2) ^ xorv));
            ldm4(af1, as + ((arowterm1 + ak2 + kb2) ^ xorv));
#pragma unroll
            for (int bt = 0; bt < 4; bt++)
                ldm4(bf[bt], bs + ((browterm[bt] + bk2 + kb2) ^ xorv));
#pragma unroll
            for (int nt = 0; nt < 8; nt++) {
                const uint32_t* bfr = &bf[nt >> 1][(nt & 1) * 2];
                mma16816(acc[0][nt], af0, bfr);
                mma16816(acc[1][nt], af1, bfr);
            }
        }
    }

    int g = lane >> 2, t4 = lane & 3;
#pragma unroll
    for (int mt = 0; mt < 2; mt++) {
        int row = bm + wm + mt * 16 + g;
#pragma unroll
        for (int nt = 0; nt < 8; nt++) {
            int col = bn + wn + nt * 8 + t4 * 2;
            float b0 = bias[col], b1 = bias[col + 1];
            float2 o0 = make_float2(acc[mt][nt][0] + b0, acc[mt][nt][1] + b1);
            float2 o1 = make_float2(acc[mt][nt][2] + b0, acc[mt][nt][3] + b1);
            *(float2*)(C + (size_t)row * DIM + col) = o0;
            *(float2*)(C + (size_t)(row + 8) * DIM + col) = o1;
        }
    }
}

// ================= prep kernels =================
__global__ void split_kernel(const float* __restrict__ in, __nv_bfloat16* __restrict__ o)
{
    size_t i = (size_t)blockIdx.x * 256 + threadIdx.x;
    size_t row = i >> 8;
    int c4 = (int)(i & 255) * 4;
    float4 v = *(const float4*)(in + row * DIM + c4);
    __nv_bfloat16 h0 = __float2bfloat16(v.x), h1 = __float2bfloat16(v.y);
    __nv_bfloat16 h2 = __float2bfloat16(v.z), h3 = __float2bfloat16(v.w);
    __nv_bfloat16 l0 = __float2bfloat16(v.x - __bfloat162float(h0));
    __nv_bfloat16 l1 = __float2bfloat16(v.y - __bfloat162float(h1));
    __nv_bfloat16 l2 = __float2bfloat16(v.z - __bfloat162float(h2));
    __nv_bfloat16 l3 = __float2bfloat16(v.w - __bfloat162float(h3));
    __nv_bfloat162* ph = (__nv_bfloat162*)(o + row * KTOT + c4);
    ph[0] = __halves2bfloat162(h0, h1);
    ph[1] = __halves2bfloat162(h2, h3);
    __nv_bfloat162* pl = (__nv_bfloat162*)(o + row * KTOT + 1024 + c4);
    pl[0] = __halves2bfloat162(l0, l1);
    pl[1] = __halves2bfloat162(l2, l3);
}

__global__ void wsplit_kernel(const float* __restrict__ W, __nv_bfloat16* __restrict__ Wt)
{
    __shared__ float sm[32][33];
    int n0 = blockIdx.x * 32, k0 = blockIdx.y * 32;
    int tid = threadIdx.x;
#pragma unroll
    for (int l = 0; l < 4; l++) {
        int idx = tid + l * 256;
        int r = idx >> 5, c = idx & 31;
        sm[r][c] = W[(size_t)(k0 + r) * DIM + n0 + c];
    }
    __syncthreads();
#pragma unroll
    for (int l = 0; l < 4; l++) {
        int idx = tid + l * 256;
        int r = idx >> 5, c = idx & 31;
        float v = sm[c][r];
        __nv_bfloat16 h = __float2bfloat16(v);
        __nv_bfloat16 lo = __float2bfloat16(v - __bfloat162float(h));
        Wt[(size_t)(n0 + r) * KTOT + k0 + c] = h;
        Wt[(size_t)(n0 + r) * KTOT + 1024 + k0 + c] = lo;
    }
}

// ================= attention mid-section =================
__global__ void softmax64_kernel(float* __restrict__ data)
{
    int gt = blockIdx.x * blockDim.x + threadIdx.x;
    int w = gt >> 5;
    int lane = threadIdx.x & 31;
    int row = w >> 4;
    int h = w & 15;
    float* p = data + (size_t)row * DIM + h * DHEAD;
    float v0 = p[lane], v1 = p[lane + 32];
    float m = fmaxf(v0, v1);
#pragma unroll
    for (int off = 16; off > 0; off >>= 1)
        m = fmaxf(m, __shfl_xor_sync(0xffffffffu, m, off));
    float e0 = __expf(v0 - m), e1 = __expf(v1 - m);
    float s = e0 + e1;
#pragma unroll
    for (int off = 16; off > 0; off >>= 1)
        s += __shfl_xor_sync(0xffffffffu, s, off);
    float inv = 1.f / s;
    p[lane] = e0 * inv;
    p[lane + 32] = e1 * inv;
}

__global__ void kcumsum_kernel(const float* __restrict__ k, float* __restrict__ kc)
{
    int bh = blockIdx.x;
    int b = bh >> 4, h = bh & 15;
    int d = threadIdx.x & 63;
    int chunk = threadIdx.x >> 6;
    const float* base = k + (size_t)(b * TSEQ + chunk * 1024) * DIM + h * DHEAD + d;
    float s = 0.f;
#pragma unroll 8
    for (int t = 0; t < 1024; t++) s += base[(size_t)t * DIM];
    __shared__ float sm[256];
    sm[threadIdx.x] = s;
    __syncthreads();
    if (threadIdx.x < 64)
        kc[bh * DHEAD + d] = sm[d] + sm[64 + d] + sm[128 + d] + sm[192 + d];
}

__global__ void ctx_partial_kernel(const float* __restrict__ k, const float* __restrict__ v,
                                   float* __restrict__ part)
{
    int chunk = blockIdx.x;
    int bh = blockIdx.y;
    int b = bh >> 4, h = bh & 15;
    int t0 = chunk * 512;
    __shared__ float ks[32][64];
    __shared__ float vs[32][64];
    int tid = threadIdx.x;
    int d0 = (tid >> 4) << 2;
    int e0 = (tid & 15) << 2;
    float acc[4][4];
#pragma unroll
    for (int i = 0; i < 4; i++)
#pragma unroll
        for (int j = 0; j < 4; j++) acc[i][j] = 0.f;

    for (int tt = 0; tt < 512; tt += 32) {
#pragma unroll
        for (int l = 0; l < 2; l++) {
            int idx = tid + l * 256;
            int r = idx >> 4;
            int c = (idx & 15) << 2;
            size_t g = (size_t)(b * TSEQ + t0 + tt + r) * DIM + h * DHEAD + c;
            *(float4*)&ks[r][c] = *(const float4*)(k + g);
            *(float4*)&vs[r][c] = *(const float4*)(v + g);
        }
        __syncthreads();
#pragma unroll 8
        for (int t = 0; t < 32; t++) {
            float4 ka = *(const float4*)&ks[t][d0];
            float4 vb = *(const float4*)&vs[t][e0];
            float a[4] = {ka.x, ka.y, ka.z, ka.w};
            float bb[4] = {vb.x, vb.y, vb.z, vb.w};
#pragma unroll
            for (int i = 0; i < 4; i++)
#pragma unroll
                for (int j = 0; j < 4; j++)
                    acc[i][j] = fmaf(a[i], bb[j], acc[i][j]);
        }
        __syncthreads();
    }
    float* outp = part + ((size_t)chunk * BHTOT + bh) * DHEAD * DHEAD;
#pragma unroll
    for (int i = 0; i < 4; i++)
        *(float4*)&outp[(d0 + i) * DHEAD + e0] =
            make_float4(acc[i][0], acc[i][1], acc[i][2], acc[i][3]);
}

__global__ void ctx_reduce_kernel(const float* __restrict__ part, float* __restrict__ ctx)
{
    int i = blockIdx.x * blockDim.x + threadIdx.x;
    const size_t stride = (size_t)BHTOT * DHEAD * DHEAD;
    float s = 0.f;
#pragma unroll
    for (int c = 0; c < 8; c++) s += part[c * stride + i];
    ctx[i] = s;
}

// y = (q @ ctx) * dinv + q, dinv computed inline, output written as hi|lo bf16 split
__global__ void apply_kernel(const float* __restrict__ q, const float* __restrict__ ctx,
                             const float* __restrict__ kc, __nv_bfloat16* __restrict__ ysplit)
{
    int bh = blockIdx.y;
    int b = bh >> 4, h = bh & 15;
    int t0 = blockIdx.x * 64;
    __shared__ float cs[64][64];
    __shared__ float qs[64][64];
    __shared__ float kcs[64];
    int tid = threadIdx.x;

    const float4* cp = (const float4*)(ctx + (size_t)bh * DHEAD * DHEAD);
#pragma unroll
    for (int l = 0; l < 4; l++)
        ((float4*)cs)[tid + l * 256] = cp[tid + l * 256];
#pragma unroll
    for (int l = 0; l < 4; l++) {
        int idx = tid + l * 256;
        int r = idx >> 4;
        int c = (idx & 15) << 2;
        *(float4*)&qs[r][c] =
            *(const float4*)(q + (size_t)(b * TSEQ + t0 + r) * DIM + h * DHEAD + c);
    }
    if (tid < 64) kcs[tid] = kc[bh * DHEAD + tid];
    __syncthreads();

    int wid = tid >> 5, lane = tid & 31;
#pragma unroll
    for (int rr = 0; rr < 8; rr++) {
        int r = wid * 8 + rr;
        float a0 = 0.f, a1 = 0.f, dk = 0.f;
#pragma unroll
        for (int d = 0; d < 64; d++) {
            float qv = qs[r][d];
            a0 = fmaf(qv, cs[d][lane], a0);
            a1 = fmaf(qv, cs[d][lane + 32], a1);
            dk = fmaf(qv, kcs[d], dk);
        }
        float di = 1.f / dk;
        int grow = b * TSEQ + t0 + r;
        float v0 = a0 * di + qs[r][lane];
        float v1 = a1 * di + qs[r][lane + 32];
        __nv_bfloat16 h0 = __float2bfloat16(v0);
        __nv_bfloat16 l0 = __float2bfloat16(v0 - __bfloat162float(h0));
        __nv_bfloat16 h1 = __float2bfloat16(v1);
        __nv_bfloat16 l1 = __float2bfloat16(v1 - __bfloat162float(h1));
        __nv_bfloat16* yp = ysplit + (size_t)grow * KTOT + h * DHEAD;
        yp[lane] = h0;
        yp[lane + 32] = h1;
        yp[1024 + lane] = l0;
        yp[1024 + lane + 32] = l1;
    }
}

// ================= launch =================
extern "C" void kernel_launch(void* const* d_in, const int* in_sizes, int n_in,
                              void* d_out, int out_size)
{
    const float* x  = (const float*)d_in[0];
    const float* Wq = (const float*)d_in[1];
    const float* bq = (const float*)d_in[2];
    const float* Wk = (const float*)d_in[3];
    const float* bk = (const float*)d_in[4];
    const float* Wv = (const float*)d_in[5];
    const float* bv = (const float*)d_in[6];
    const float* Wp = (const float*)d_in[7];
    const float* bp = (const float*)d_in[8];
    float* out = (float*)d_out;

    float *pq, *pk, *pv, *pkc, *pctx, *ppart;
    __nv_bfloat16 *psplit, *pwt;
    cudaGetSymbolAddress((void**)&pq, g_q);
    cudaGetSymbolAddress((void**)&pk, g_k);
    cudaGetSymbolAddress((void**)&pv, g_v);
    cudaGetSymbolAddress((void**)&pkc, g_kc);
    cudaGetSymbolAddress((void**)&pctx, g_ctx);
    cudaGetSymbolAddress((void**)&ppart, g_ctx_part);
    cudaGetSymbolAddress((void**)&psplit, g_split);
    cudaGetSymbolAddress((void**)&pwt, g_wt);
    __nv_bfloat16* wt0 = pwt;
    __nv_bfloat16* wt1 = pwt + (size_t)DIM * KTOT;
    __nv_bfloat16* wt2 = pwt + 2 * (size_t)DIM * KTOT;
    __nv_bfloat16* wt3 = pwt + 3 * (size_t)DIM * KTOT;

    cudaFuncSetAttribute(gemm_bf16_kernel,
                         cudaFuncAttributeMaxDynamicSharedMemorySize, GEMM_SMEM);

    split_kernel<<<MROWS * DIM / 1024, 256>>>(x, psplit);
    wsplit_kernel<<<dim3(32, 32), 256>>>(Wq, wt0);
    wsplit_kernel<<<dim3(32, 32), 256>>>(Wk, wt1);
    wsplit_kernel<<<dim3(32, 32), 256>>>(Wv, wt2);
    wsplit_kernel<<<dim3(32, 32), 256>>>(Wp, wt3);

    dim3 ggrid(DIM / 128, MROWS / 128);   // (8, 128)
    gemm_bf16_kernel<<<ggrid, 256, GEMM_SMEM>>>(psplit, wt0, bq, pq);
    gemm_bf16_kernel<<<ggrid, 256, GEMM_SMEM>>>(psplit, wt1, bk, pk);
    gemm_bf16_kernel<<<ggrid, 256, GEMM_SMEM>>>(psplit, wt2, bv, pv);

    int sm_blocks = (MROWS * HEADS * 32) / 256;
    softmax64_kernel<<<sm_blocks, 256>>>(pq);
    softmax64_kernel<<<sm_blocks, 256>>>(pk);
    kcumsum_kernel<<<BHTOT, 256>>>(pk, pkc);
    ctx_partial_kernel<<<dim3(8, BHTOT), 256>>>(pk, pv, ppart);
    ctx_reduce_kernel<<<(BHTOT * DHEAD * DHEAD) / 256, 256>>>(ppart, pctx);
    apply_kernel<<<dim3(TSEQ / 64, BHTOT), 256>>>(pq, pctx, pkc, psplit);

    gemm_bf16_kernel<<<ggrid, 256, GEMM_SMEM>>>(psplit, wt3, bp, out);
}

// round 17
// speedup vs baseline: 3.9372x; 2.0107x over previous
#include <cuda_runtime.h>
#include <cuda_fp16.h>
#include <cstdint>
#include <cstddef>

#define BATCH 4
#define TSEQ  4096
#define DIM   1024
#define HEADS 16
#define DHEAD 64
#define MROWS (BATCH * TSEQ)          // 16384
#define BHTOT (BATCH * HEADS)         // 64
#define NCHUNK 16                     // K=1024 in chunks of 64
#define NSTAGE 3
#define GEMM_SMEM 98304               // A[3][16KB] + B[3][16KB]
#define SA(s) ((s) * 16384)
#define SB(s) (49152 + (s) * 16384)

// ---------------- scratch (static device globals; no allocation) ----------------
__device__ float g_q[(size_t)MROWS * DIM];
__device__ float g_k[(size_t)MROWS * DIM];
__device__ float g_v[(size_t)MROWS * DIM];
__device__ float g_kc[BHTOT * DHEAD];
__device__ float g_ctx[BHTOT * DHEAD * DHEAD];
__device__ float g_ctx_part[8 * BHTOT * DHEAD * DHEAD];
__device__ __half g_xh[(size_t)MROWS * DIM];      // x or y in fp16
__device__ __half g_wt[4][(size_t)DIM * DIM];     // Wt fp16 (K-major, transposed)

// ================= PTX helpers (all plain sm_80-era features) =================
__device__ __forceinline__ uint32_t smem_u32(const void* p) {
    uint32_t a;
    asm("{ .reg .u64 t; cvta.to.shared.u64 t, %1; cvt.u32.u64 %0, t; }" : "=r"(a) : "l"(p));
    return a;
}
__device__ __forceinline__ void cp16(uint32_t sa, const void* ga) {
    asm volatile("cp.async.cg.shared.global [%0], [%1], 16;" :: "r"(sa), "l"(ga) : "memory");
}
__device__ __forceinline__ void ldm4(uint32_t* r, uint32_t addr) {
    asm volatile("ldmatrix.sync.aligned.m8n8.x4.shared.b16 {%0,%1,%2,%3}, [%4];"
                 : "=r"(r[0]), "=r"(r[1]), "=r"(r[2]), "=r"(r[3]) : "r"(addr));
}
__device__ __forceinline__ void mma16816(float* c, const uint32_t* a, const uint32_t* b) {
    asm volatile("mma.sync.aligned.m16n8k16.row.col.f32.f16.f16.f32 "
                 "{%0,%1,%2,%3}, {%4,%5,%6,%7}, {%8,%9}, {%0,%1,%2,%3};"
                 : "+f"(c[0]), "+f"(c[1]), "+f"(c[2]), "+f"(c[3])
                 : "r"(a[0]), "r"(a[1]), "r"(a[2]), "r"(a[3]), "r"(b[0]), "r"(b[1]));
}

// loader: A tile 128x64 fp16 + B tile 128x64 fp16 into stage chunk%3, swizzled
__device__ __forceinline__ void produce_chunk(const __half* __restrict__ agbase,
                                              const __half* __restrict__ bgbase,
                                              uint32_t sb, const uint32_t* loff, int chunk)
{
    int koff = chunk * 64;
    int s = chunk % NSTAGE;
    uint32_t abase = sb + SA(s), bbase = sb + SB(s);
#pragma unroll
    for (int g = 0; g < 4; g++) {
        cp16(abase + loff[g], agbase + koff + g * 8);
        cp16(bbase + loff[g], bgbase + koff + g * 8);
    }
    asm volatile("cp.async.commit_group;" ::: "memory");
}

// ================= fp16 GEMM via mma.sync (3-stage pipeline) =================
// C[M,1024] = A[M,1024] x Wt[N,1024]^T + bias, fp32 out
__global__ __launch_bounds__(256)
void gemm_fp16_kernel(const __half* __restrict__ A, const __half* __restrict__ B,
                      const float* __restrict__ bias, float* __restrict__ C)
{
    extern __shared__ __align__(1024) char smem[];
    uint32_t sb = smem_u32(smem);
    int tid = threadIdx.x;
    int bm = blockIdx.y * 128;
    int bn = blockIdx.x * 128;

    int lrow = tid >> 1, lhalf = tid & 1;
    const __half* agbase = A + (size_t)(bm + lrow) * DIM + lhalf * 32;
    const __half* bgbase = B + (size_t)(bn + lrow) * DIM + lhalf * 32;
    uint32_t loff[4];
#pragma unroll
    for (int g = 0; g < 4; g++)
        loff[g] = (uint32_t)(lrow * 128 + lhalf * 64 + g * 16) ^ ((uint32_t)(lrow & 7) << 4);

    int lane = tid & 31, warp = tid >> 5;
    int wm = (warp & 3) * 32;
    int wn = (warp >> 2) * 64;
    int sel = lane >> 3, lr = lane & 7;
    uint32_t xorv = (uint32_t)lr << 4;
    int arow = wm + (sel & 1) * 8 + lr;
    uint32_t arowterm0 = (uint32_t)arow * 128;
    uint32_t arowterm1 = (uint32_t)(arow + 16) * 128;
    uint32_t ak2 = (uint32_t)((sel >> 1) * 8) * 2;
    int brow = wn + (sel >> 1) * 8 + lr;
    uint32_t bk2 = (uint32_t)((sel & 1) * 8) * 2;
    uint32_t browterm[4];
#pragma unroll
    for (int bt = 0; bt < 4; bt++) browterm[bt] = (uint32_t)(brow + bt * 16) * 128;

    float acc[2][8][4];
#pragma unroll
    for (int i = 0; i < 2; i++)
#pragma unroll
        for (int j = 0; j < 8; j++)
#pragma unroll
            for (int q = 0; q < 4; q++) acc[i][j][q] = 0.f;

    produce_chunk(agbase, bgbase, sb, loff, 0);
    produce_chunk(agbase, bgbase, sb, loff, 1);

    for (int j = 0; j < NCHUNK; j++) {
        if (j < NCHUNK - 1) asm volatile("cp.async.wait_group 1;" ::: "memory");
        else                asm volatile("cp.async.wait_group 0;" ::: "memory");
        __syncthreads();
        if (j + 2 < NCHUNK) produce_chunk(agbase, bgbase, sb, loff, j + 2);

        int s = j % NSTAGE;
        uint32_t as = sb + SA(s);
        uint32_t bs = sb + SB(s);
#pragma unroll
        for (uint32_t kb2 = 0; kb2 < 128; kb2 += 32) {
            uint32_t af0[4], af1[4], bf[4][4];
            ldm4(af0, as + ((arowterm0 + ak2 + kb2) ^ xorv));
            ldm4(af1, as + ((arowterm1 + ak2 + kb2) ^ xorv));
#pragma unroll
            for (int bt = 0; bt < 4; bt++)
                ldm4(bf[bt], bs + ((browterm[bt] + bk2 + kb2) ^ xorv));
#pragma unroll
            for (int nt = 0; nt < 8; nt++) {
                const uint32_t* bfr = &bf[nt >> 1][(nt & 1) * 2];
                mma16816(acc[0][nt], af0, bfr);
                mma16816(acc[1][nt], af1, bfr);
            }
        }
    }

    int g = lane >> 2, t4 = lane & 3;
#pragma unroll
    for (int mt = 0; mt < 2; mt++) {
        int row = bm + wm + mt * 16 + g;
#pragma unroll
        for (int nt = 0; nt < 8; nt++) {
            int col = bn + wn + nt * 8 + t4 * 2;
            float b0 = bias[col], b1 = bias[col + 1];
            float2 o0 = make_float2(acc[mt][nt][0] + b0, acc[mt][nt][1] + b1);
            float2 o1 = make_float2(acc[mt][nt][2] + b0, acc[mt][nt][3] + b1);
            *(float2*)(C + (size_t)row * DIM + col) = o0;
            *(float2*)(C + (size_t)(row + 8) * DIM + col) = o1;
        }
    }
}

// ================= prep kernels =================
// convert fp32 [rows,1024] -> fp16
__global__ void conv_kernel(const float* __restrict__ in, __half* __restrict__ o)
{
    size_t i = (size_t)blockIdx.x * 256 + threadIdx.x;   // one float4 each
    float4 v = *(const float4*)(in + i * 4);
    __half2 h0 = __floats2half2_rn(v.x, v.y);
    __half2 h1 = __floats2half2_rn(v.z, v.w);
    __half2* p = (__half2*)(o + i * 4);
    p[0] = h0;
    p[1] = h1;
}

// transpose + convert: W[K=1024,N=1024] -> Wt[N,1024] fp16 (K-major)
__global__ void wconv_kernel(const float* __restrict__ W, __half* __restrict__ Wt)
{
    __shared__ float sm[32][33];
    int n0 = blockIdx.x * 32, k0 = blockIdx.y * 32;
    int tid = threadIdx.x;
#pragma unroll
    for (int l = 0; l < 4; l++) {
        int idx = tid + l * 256;
        int r = idx >> 5, c = idx & 31;
        sm[r][c] = W[(size_t)(k0 + r) * DIM + n0 + c];
    }
    __syncthreads();
#pragma unroll
    for (int l = 0; l < 4; l++) {
        int idx = tid + l * 256;
        int r = idx >> 5, c = idx & 31;
        Wt[(size_t)(n0 + r) * DIM + k0 + c] = __float2half_rn(sm[c][r]);
    }
}

// ================= attention mid-section =================
__global__ void softmax64_kernel(float* __restrict__ data)
{
    int gt = blockIdx.x * blockDim.x + threadIdx.x;
    int w = gt >> 5;
    int lane = threadIdx.x & 31;
    int row = w >> 4;
    int h = w & 15;
    float* p = data + (size_t)row * DIM + h * DHEAD;
    float v0 = p[lane], v1 = p[lane + 32];
    float m = fmaxf(v0, v1);
#pragma unroll
    for (int off = 16; off > 0; off >>= 1)
        m = fmaxf(m, __shfl_xor_sync(0xffffffffu, m, off));
    float e0 = __expf(v0 - m), e1 = __expf(v1 - m);
    float s = e0 + e1;
#pragma unroll
    for (int off = 16; off > 0; off >>= 1)
        s += __shfl_xor_sync(0xffffffffu, s, off);
    float inv = 1.f / s;
    p[lane] = e0 * inv;
    p[lane + 32] = e1 * inv;
}

__global__ void kcumsum_kernel(const float* __restrict__ k, float* __restrict__ kc)
{
    int bh = blockIdx.x;
    int b = bh >> 4, h = bh & 15;
    int d = threadIdx.x & 63;
    int chunk = threadIdx.x >> 6;
    const float* base = k + (size_t)(b * TSEQ + chunk * 1024) * DIM + h * DHEAD + d;
    float s = 0.f;
#pragma unroll 8
    for (int t = 0; t < 1024; t++) s += base[(size_t)t * DIM];
    __shared__ float sm[256];
    sm[threadIdx.x] = s;
    __syncthreads();
    if (threadIdx.x < 64)
        kc[bh * DHEAD + d] = sm[d] + sm[64 + d] + sm[128 + d] + sm[192 + d];
}

__global__ void ctx_partial_kernel(const float* __restrict__ k, const float* __restrict__ v,
                                   float* __restrict__ part)
{
    int chunk = blockIdx.x;
    int bh = blockIdx.y;
    int b = bh >> 4, h = bh & 15;
    int t0 = chunk * 512;
    __shared__ float ks[32][64];
    __shared__ float vs[32][64];
    int tid = threadIdx.x;
    int d0 = (tid >> 4) << 2;
    int e0 = (tid & 15) << 2;
    float acc[4][4];
#pragma unroll
    for (int i = 0; i < 4; i++)
#pragma unroll
        for (int j = 0; j < 4; j++) acc[i][j] = 0.f;

    for (int tt = 0; tt < 512; tt += 32) {
#pragma unroll
        for (int l = 0; l < 2; l++) {
            int idx = tid + l * 256;
            int r = idx >> 4;
            int c = (idx & 15) << 2;
            size_t g = (size_t)(b * TSEQ + t0 + tt + r) * DIM + h * DHEAD + c;
            *(float4*)&ks[r][c] = *(const float4*)(k + g);
            *(float4*)&vs[r][c] = *(const float4*)(v + g);
        }
        __syncthreads();
#pragma unroll 8
        for (int t = 0; t < 32; t++) {
            float4 ka = *(const float4*)&ks[t][d0];
            float4 vb = *(const float4*)&vs[t][e0];
            float a[4] = {ka.x, ka.y, ka.z, ka.w};
            float bb[4] = {vb.x, vb.y, vb.z, vb.w};
#pragma unroll
            for (int i = 0; i < 4; i++)
#pragma unroll
                for (int j = 0; j < 4; j++)
                    acc[i][j] = fmaf(a[i], bb[j], acc[i][j]);
        }
        __syncthreads();
    }
    float* outp = part + ((size_t)chunk * BHTOT + bh) * DHEAD * DHEAD;
#pragma unroll
    for (int i = 0; i < 4; i++)
        *(float4*)&outp[(d0 + i) * DHEAD + e0] =
            make_float4(acc[i][0], acc[i][1], acc[i][2], acc[i][3]);
}

__global__ void ctx_reduce_kernel(const float* __restrict__ part, float* __restrict__ ctx)
{
    int i = blockIdx.x * blockDim.x + threadIdx.x;
    const size_t stride = (size_t)BHTOT * DHEAD * DHEAD;
    float s = 0.f;
#pragma unroll
    for (int c = 0; c < 8; c++) s += part[c * stride + i];
    ctx[i] = s;
}

// y = (q @ ctx) * dinv + q, dinv inline, output written as fp16 (merged-head layout)
__global__ void apply_kernel(const float* __restrict__ q, const float* __restrict__ ctx,
                             const float* __restrict__ kc, __half* __restrict__ yh)
{
    int bh = blockIdx.y;
    int b = bh >> 4, h = bh & 15;
    int t0 = blockIdx.x * 64;
    __shared__ float cs[64][64];
    __shared__ float qs[64][64];
    __shared__ float kcs[64];
    int tid = threadIdx.x;

    const float4* cp = (const float4*)(ctx + (size_t)bh * DHEAD * DHEAD);
#pragma unroll
    for (int l = 0; l < 4; l++)
        ((float4*)cs)[tid + l * 256] = cp[tid + l * 256];
#pragma unroll
    for (int l = 0; l < 4; l++) {
        int idx = tid + l * 256;
        int r = idx >> 4;
        int c = (idx & 15) << 2;
        *(float4*)&qs[r][c] =
            *(const float4*)(q + (size_t)(b * TSEQ + t0 + r) * DIM + h * DHEAD + c);
    }
    if (tid < 64) kcs[tid] = kc[bh * DHEAD + tid];
    __syncthreads();

    int wid = tid >> 5, lane = tid & 31;
#pragma unroll
    for (int rr = 0; rr < 8; rr++) {
        int r = wid * 8 + rr;
        float a0 = 0.f, a1 = 0.f, dk = 0.f;
#pragma unroll
        for (int d = 0; d < 64; d++) {
            float qv = qs[r][d];
            a0 = fmaf(qv, cs[d][lane], a0);
            a1 = fmaf(qv, cs[d][lane + 32], a1);
            dk = fmaf(qv, kcs[d], dk);
        }
        float di = 1.f / dk;
        int grow = b * TSEQ + t0 + r;
        float v0 = a0 * di + qs[r][lane];
        float v1 = a1 * di + qs[r][lane + 32];
        __half* yp = yh + (size_t)grow * DIM + h * DHEAD;
        yp[lane] = __float2half_rn(v0);
        yp[lane + 32] = __float2half_rn(v1);
    }
}

// ================= launch =================
extern "C" void kernel_launch(void* const* d_in, const int* in_sizes, int n_in,
                              void* d_out, int out_size)
{
    const float* x  = (const float*)d_in[0];
    const float* Wq = (const float*)d_in[1];
    const float* bq = (const float*)d_in[2];
    const float* Wk = (const float*)d_in[3];
    const float* bk = (const float*)d_in[4];
    const float* Wv = (const float*)d_in[5];
    const float* bv = (const float*)d_in[6];
    const float* Wp = (const float*)d_in[7];
    const float* bp = (const float*)d_in[8];
    float* out = (float*)d_out;

    float *pq, *pk, *pv, *pkc, *pctx, *ppart;
    __half *pxh, *pwt;
    cudaGetSymbolAddress((void**)&pq, g_q);
    cudaGetSymbolAddress((void**)&pk, g_k);
    cudaGetSymbolAddress((void**)&pv, g_v);
    cudaGetSymbolAddress((void**)&pkc, g_kc);
    cudaGetSymbolAddress((void**)&pctx, g_ctx);
    cudaGetSymbolAddress((void**)&ppart, g_ctx_part);
    cudaGetSymbolAddress((void**)&pxh, g_xh);
    cudaGetSymbolAddress((void**)&pwt, g_wt);
    __half* wt0 = pwt;
    __half* wt1 = pwt + (size_t)DIM * DIM;
    __half* wt2 = pwt + 2 * (size_t)DIM * DIM;
    __half* wt3 = pwt + 3 * (size_t)DIM * DIM;

    cudaFuncSetAttribute(gemm_fp16_kernel,
                         cudaFuncAttributeMaxDynamicSharedMemorySize, GEMM_SMEM);

    conv_kernel<<<MROWS * DIM / 1024, 256>>>(x, pxh);
    wconv_kernel<<<dim3(32, 32), 256>>>(Wq, wt0);
    wconv_kernel<<<dim3(32, 32), 256>>>(Wk, wt1);
    wconv_kernel<<<dim3(32, 32), 256>>>(Wv, wt2);
    wconv_kernel<<<dim3(32, 32), 256>>>(Wp, wt3);

    dim3 ggrid(DIM / 128, MROWS / 128);   // (8, 128)
    gemm_fp16_kernel<<<ggrid, 256, GEMM_SMEM>>>(pxh, wt0, bq, pq);
    gemm_fp16_kernel<<<ggrid, 256, GEMM_SMEM>>>(pxh, wt1, bk, pk);
    gemm_fp16_kernel<<<ggrid, 256, GEMM_SMEM>>>(pxh, wt2, bv, pv);

    int sm_blocks = (MROWS * HEADS * 32) / 256;
    softmax64_kernel<<<sm_blocks, 256>>>(pq);
    softmax64_kernel<<<sm_blocks, 256>>>(pk);
    kcumsum_kernel<<<BHTOT, 256>>>(pk, pkc);
    ctx_partial_kernel<<<dim3(8, BHTOT), 256>>>(pk, pv, ppart);
    ctx_reduce_kernel<<<(BHTOT * DHEAD * DHEAD) / 256, 256>>>(ppart, pctx);
    apply_kernel<<<dim3(TSEQ / 64, BHTOT), 256>>>(pq, pctx, pkc, pxh);

    gemm_fp16_kernel<<<ggrid, 256, GEMM_SMEM>>>(pxh, wt3, bp, out);
}